// round 7
// baseline (speedup 1.0000x reference)
#include <cuda_runtime.h>
#include <math.h>

// B=8, D=64, O=256, I=256, G=128
// Output: V(8) | A(8*65536) | hn(8*64) | cn(8*64)
#define OFF_V  0
#define OFF_A  8
#define OFF_HN 524296
#define OFF_CN 524808

#define NBLK 128

// ---- scratch ----
__device__ float g_hn[8 * 64];
__device__ float g_u[8 * 128];
__device__ float g_pc[8];
__device__ float g_M[4 * 128 * 64];     // m0=Wa1@Wo, m1=Wa1@Wi, m2=Wa1@Ws, m3=Wv1@Wv0
__device__ float g_bba[128];
__device__ float g_bbv[128];
__device__ float g_c1[128];
__device__ float g_c2d[256];
__device__ float g_vvT[8 * 128 * 256];  // [b][g][o]
__device__ float g_wT[8 * 128 * 256];   // [b][g][i]
__device__ float g_PQ[4096];
__device__ float g_dummy[NBLK];

// ---- grid barrier (sense via generation counter; replay-safe) ----
__device__ unsigned g_barcnt = 0;
__device__ volatile unsigned g_bargen = 0;

__device__ __forceinline__ void grid_barrier() {
    __syncthreads();
    if (threadIdx.x == 0) {
        __threadfence();
        unsigned gen = g_bargen;
        if (atomicAdd(&g_barcnt, 1) == (unsigned)(gridDim.x - 1)) {
            g_barcnt = 0;
            __threadfence();
            g_bargen = gen + 1;
        } else {
            while (g_bargen == gen) { __nanosleep(64); }
        }
        __threadfence();
    }
    __syncthreads();
}

__device__ __forceinline__ float sigm(float x) { return 1.0f / (1.0f + expf(-x)); }

__device__ __forceinline__ float warp_sum(float v) {
    #pragma unroll
    for (int o = 16; o; o >>= 1) v += __shfl_xor_sync(0xffffffffu, v, o);
    return v;
}

__device__ __forceinline__ unsigned long long addp(unsigned long long a, unsigned long long b) {
    unsigned long long r;
    asm("add.rn.f32x2 %0, %1, %2;" : "=l"(r) : "l"(a), "l"(b));
    return r;
}
__device__ __forceinline__ unsigned long long fmap(unsigned long long a, unsigned long long b, unsigned long long c) {
    unsigned long long r;
    asm("fma.rn.f32x2 %0, %1, %2, %3;" : "=l"(r) : "l"(a), "l"(b), "l"(c));
    return r;
}

// ============================================================
// One persistent kernel, 3 phases separated by grid barriers.
// ============================================================
__global__ void __launch_bounds__(256) k_all(
        const float* __restrict__ ope,  const float* __restrict__ ins,
        const float* __restrict__ h_in, const float* __restrict__ c_in,
        const float* __restrict__ W_ih, const float* __restrict__ W_hh,
        const float* __restrict__ b_ih, const float* __restrict__ b_hh,
        const float* __restrict__ Wv0,  const float* __restrict__ bv0,
        const float* __restrict__ Wv1,  const float* __restrict__ bv1,
        const float* __restrict__ Wv2,  const float* __restrict__ bv2,
        const float* __restrict__ Wa0,  const float* __restrict__ ba0,
        const float* __restrict__ Wa1,  const float* __restrict__ ba1,
        const float* __restrict__ Wa2,  const float* __restrict__ ba2p,
        float* __restrict__ out)
{
    extern __shared__ float dsm[];
    const int bid = blockIdx.x;
    const int t = threadIdx.x;

    // ================= PHASE 1 =================
    if (bid < 32) {
        // GEMM tasks: g_M[m] for m = bid>>3, 16-row g chunk gc = bid&7
        float* sA = dsm;                 // 16*129
        float* sB = dsm + 16 * 129;      // 128*72
        const int m  = bid >> 3;
        const int gc = bid & 7;

        const float* Aglob = (m == 3) ? Wv1 : Wa1;
        #pragma unroll
        for (int i = 0; i < 8; i++) {
            int idx = t + i * 256;
            sA[(idx >> 7) * 129 + (idx & 127)] = Aglob[gc * 2048 + idx];
        }
        {
            int hh0 = t >> 4, c4 = t & 15;
            #pragma unroll
            for (int i = 0; i < 8; i++) {
                int hh = hh0 + i * 16;
                const float* src = (m == 3) ? (Wv0 + hh * 64)
                                            : (Wa0 + hh * 192 + ((m == 0) ? 64 : (m == 1) ? 128 : 0));
                float4 v = *(const float4*)(src + c4 * 4);
                *(float4*)(sB + hh * 72 + c4 * 4) = v;
            }
        }
        __syncthreads();

        const int g = t >> 4, dg = t & 15;
        float4 acc = make_float4(0.f, 0.f, 0.f, 0.f);
        const float* arow = sA + g * 129;
        const float* bcol = sB + dg * 4;
        #pragma unroll 8
        for (int hh = 0; hh < 128; hh++) {
            float a = arow[hh];
            float4 bv = *(const float4*)(bcol + hh * 72);
            acc.x += a * bv.x; acc.y += a * bv.y; acc.z += a * bv.z; acc.w += a * bv.w;
        }
        *(float4*)(g_M + m * 8192 + (gc * 16 + g) * 64 + dg * 4) = acc;
    }
    else if (bid == 32) {
        // biases + c1/c2d
        __shared__ float sb[256];
        if (t < 128) sb[t] = ba0[t];
        else         sb[t] = bv0[t - 128];
        __syncthreads();
        if (t < 128) {
            float acc = ba1[t];
            const float4* row = (const float4*)(Wa1 + t * 128);
            #pragma unroll 8
            for (int j = 0; j < 32; j++) {
                float4 w4 = row[j];
                float4 x4 = *(const float4*)(sb + j * 4);
                acc += w4.x * x4.x + w4.y * x4.y + w4.z * x4.z + w4.w * x4.w;
            }
            g_bba[t] = acc;
            float w2 = Wa2[t];
            g_c1[t] = 0.505f * w2;
            g_c2d[2 * t]     = 0.495f * w2;
            g_c2d[2 * t + 1] = 0.495f * w2;
        } else {
            int r = t - 128;
            float acc = bv1[r];
            const float4* row = (const float4*)(Wv1 + r * 128);
            #pragma unroll 8
            for (int j = 0; j < 32; j++) {
                float4 w4 = row[j];
                float4 x4 = *(const float4*)(sb + 128 + j * 4);
                acc += w4.x * x4.x + w4.y * x4.y + w4.z * x4.z + w4.w * x4.w;
            }
            g_bbv[r] = acc;
        }
    }
    else if (bid < 41) {
        // per-batch mean / gates (weights in registers) / LSTM
        __shared__ float sPart[1024];
        __shared__ float s_x[128];
        __shared__ float s_gates[256];
        const int b = bid - 33;

        // prefetch W_ih row t into registers (one DRAM latency, overlapped with mean)
        float4 wi[16];
        {
            const float4* pwi = (const float4*)(W_ih + t * 64);
            #pragma unroll
            for (int j = 0; j < 16; j++) wi[j] = pwi[j];
        }

        {
            int dq = t & 15, rc = t >> 4;
            const float* base = ope + (b * 258 + 1 + rc * 16) * 64 + dq * 4;
            float4 s = make_float4(0.f, 0.f, 0.f, 0.f);
            #pragma unroll
            for (int rr = 0; rr < 16; rr++) {
                float4 x = *(const float4*)(base + rr * 64);
                s.x += x.x; s.y += x.y; s.z += x.z; s.w += x.w;
            }
            *(float4*)(sPart + rc * 64 + dq * 4) = s;
        }
        if (t >= 64 && t < 128) s_x[t] = h_in[b * 64 + (t - 64)];
        __syncthreads();
        if (t < 64) {
            float s = 0.f;
            #pragma unroll
            for (int rc = 0; rc < 16; rc++) s += sPart[rc * 64 + t];
            s_x[t] = s * (1.0f / 256.0f);
        }
        __syncthreads();

        float acc = b_ih[t] + b_hh[t];
        #pragma unroll
        for (int j = 0; j < 16; j++) {
            float4 x4 = *(const float4*)(s_x + j * 4);
            acc += wi[j].x * x4.x + wi[j].y * x4.y + wi[j].z * x4.z + wi[j].w * x4.w;
        }
        {
            float4 wh[16];
            const float4* pwh = (const float4*)(W_hh + t * 64);
            #pragma unroll
            for (int j = 0; j < 16; j++) wh[j] = pwh[j];
            #pragma unroll
            for (int j = 0; j < 16; j++) {
                float4 x4 = *(const float4*)(s_x + 64 + j * 4);
                acc += wh[j].x * x4.x + wh[j].y * x4.y + wh[j].z * x4.z + wh[j].w * x4.w;
            }
        }
        s_gates[t] = acc;
        __syncthreads();

        if (t < 64) {
            float ig = sigm(s_gates[t]);
            float fg = sigm(s_gates[64 + t]);
            float gg = tanhf(s_gates[128 + t]);
            float og = sigm(s_gates[192 + t]);
            float cn = fg * c_in[b * 64 + t] + ig * gg;
            float hn = og * tanhf(cn);
            g_hn[b * 64 + t] = hn;
            out[OFF_HN + b * 64 + t] = hn;
            out[OFF_CN + b * 64 + t] = cn;
        }
    }
    else {
        // idle blocks: prefetch ope/ins into L2 for phase 2
        const int nb = NBLK - 41;
        const int me = bid - 41;
        float s = 0.f;
        const float4* o4 = (const float4*)ope;
        const float4* i4 = (const float4*)ins;
        for (int i = me * 256 + t; i < 33024; i += nb * 256) { float4 x = o4[i]; s += x.x + x.w; }
        for (int i = me * 256 + t; i < 32768; i += nb * 256) { float4 x = i4[i]; s += x.x + x.w; }
        if (t == 0) g_dummy[me] = s;
    }

    grid_barrier();

    // ================= PHASE 2 =================
    for (int task = bid; task < 264; task += NBLK) {
        if (task < 256) {
            float* sIn  = dsm;          // 1024
            float* sRed = dsm + 1024;   // 2048
            const int rbase = task * 16;
            const int g = t;
            const bool isV = (rbase < 2048);
            const int rb = isV ? rbase : (rbase - 2048);
            const int b = rb >> 8;
            const int x0 = rb & 255;

            const float4* Mrow = (const float4*)(g_M + (isV ? 0 : 8192) + g * 64);
            float4 m[16];
            #pragma unroll
            for (int j = 0; j < 16; j++) m[j] = Mrow[j];

            const float4* s4 = (const float4*)(isV ? (ope + (b * 258 + 1 + x0) * 64)
                                                   : (ins + (b * 256 + x0) * 64));
            if (t < 128) {
                ((float4*)sIn)[g] = s4[g];
                ((float4*)sIn)[g + 128] = s4[g + 128];
            }
            const float c1 = g_c1[g];
            __syncthreads();

            if (t < 128) {
                float accs[16];
                #pragma unroll
                for (int r = 0; r < 16; r++) {
                    float a = 0.f;
                    const float4* ip = (const float4*)(sIn + r * 64);
                    #pragma unroll
                    for (int j = 0; j < 16; j++) {
                        float4 x = ip[j];
                        a += m[j].x * x.x + m[j].y * x.y + m[j].z * x.z + m[j].w * x.w;
                    }
                    accs[r] = a;
                    sRed[r * 128 + g] = c1 * a;
                }
                float* dst = (isV ? g_vvT : g_wT) + b * 32768 + g * 256 + x0;
                #pragma unroll
                for (int r4 = 0; r4 < 4; r4++)
                    *(float4*)(dst + r4 * 4) = make_float4(accs[r4*4], accs[r4*4+1], accs[r4*4+2], accs[r4*4+3]);
            }
            __syncthreads();
            if (t < 128) {
                int ww = t >> 5, lane = t & 31;
                #pragma unroll
                for (int rr = 0; rr < 4; rr++) {
                    int row = ww * 4 + rr;
                    float4 xx = ((const float4*)(sRed + row * 128))[lane];
                    float s = xx.x + xx.y + xx.z + xx.w;
                    #pragma unroll
                    for (int off = 16; off; off >>= 1) s += __shfl_xor_sync(0xffffffffu, s, off);
                    if (lane == 0) g_PQ[rbase + row] = s;
                }
            }
            __syncthreads();
        } else {
            // u / pc / V per batch
            __shared__ float shn[64];
            __shared__ float spc[128];
            __shared__ float sz[128];
            const int b = task - 256;
            if (t < 64) shn[t] = g_hn[b * 64 + t];
            __syncthreads();
            if (t < 128) {
                {
                    float acc = g_bba[t];
                    const float4* row = (const float4*)(g_M + 2 * 8192 + t * 64);
                    #pragma unroll
                    for (int j = 0; j < 16; j++) {
                        float4 w4 = row[j];
                        float4 x4 = *(const float4*)(shn + j * 4);
                        acc += w4.x * x4.x + w4.y * x4.y + w4.z * x4.z + w4.w * x4.w;
                    }
                    g_u[b * 128 + t] = acc;
                    spc[t] = g_c1[t] * acc;
                }
                {
                    float acc = g_bbv[t];
                    const float4* row = (const float4*)(g_M + 3 * 8192 + t * 64);
                    #pragma unroll
                    for (int j = 0; j < 16; j++) {
                        float4 w4 = row[j];
                        float4 x4 = *(const float4*)(shn + j * 4);
                        acc += w4.x * x4.x + w4.y * x4.y + w4.z * x4.z + w4.w * x4.w;
                    }
                    sz[t] = (acc >= 0.f) ? acc : 0.01f * acc;
                }
            }
            __syncthreads();
            int w = t >> 5, lane = t & 31;
            if (w == 0) {
                float4 x = *(const float4*)(spc + lane * 4);
                float s = x.x + x.y + x.z + x.w;
                s = warp_sum(s);
                if (lane == 0) g_pc[b] = s;
            } else if (w == 1) {
                float4 x = *(const float4*)(sz + lane * 4);
                float4 ww = *(const float4*)(Wv2 + lane * 4);
                float s = ww.x * x.x + ww.y * x.y + ww.z * x.z + ww.w * x.w;
                s = warp_sum(s);
                if (lane == 0) out[OFF_V + b] = s + bv2[0];
            }
            __syncthreads();
        }
    }

    grid_barrier();

    // ================= PHASE 3 (A tiles) =================
    {
        float* sVd = dsm;            // 128*128
        float* sW  = dsm + 16384;    // 128*64
        float* sC2 = dsm + 24576;    // 256
        float* sP  = dsm + 24832;    // 64
        float* sQ  = dsm + 24896;    // 64
        const int b = bid >> 4, oc = (bid >> 2) & 3, ic = bid & 3;

        const float pcb = g_pc[b] + ba2p[0];

        const float* vsrc = g_vvT + b * 32768 + oc * 64;
        const float* wsrc = g_wT  + b * 32768 + ic * 64;
        const float* usrc = g_u + b * 128;
        #pragma unroll
        for (int l = t; l < 2048; l += 256) {
            int gg = l >> 4, q = (l & 15) << 2;
            float4 wv = *(const float4*)(wsrc + gg * 256 + q);
            *(float4*)(sW + gg * 64 + q) = wv;
            float uu = usrc[gg];
            float4 vv = *(const float4*)(vsrc + gg * 256 + q);
            vv.x += uu; vv.y += uu; vv.z += uu; vv.w += uu;
            float* vd = sVd + gg * 128 + q * 2;
            ((float4*)vd)[0] = make_float4(vv.x, vv.x, vv.y, vv.y);
            ((float4*)vd)[1] = make_float4(vv.z, vv.z, vv.w, vv.w);
        }
        sC2[t] = g_c2d[t & 255];
        if (t < 64)       sP[t] = g_PQ[b * 256 + oc * 64 + t];
        else if (t < 128) sQ[t - 64] = g_PQ[2048 + b * 256 + ic * 64 + (t - 64)];
        __syncthreads();

        const int tx = t & 15, ty = t >> 4;
        unsigned long long a00 = 0, a01 = 0, a10 = 0, a11 = 0,
                           a20 = 0, a21 = 0, a30 = 0, a31 = 0;
        const float* vbase = sVd + ty * 8;
        const float* wbase = sW + tx * 4;
        const unsigned long long* c2base = (const unsigned long long*)sC2;
        const unsigned long long MASK = 0x7FFFFFFF7FFFFFFFULL;

        #pragma unroll 4
        for (int gg = 0; gg < 128; gg++) {
            ulonglong2 vp01 = *(const ulonglong2*)(vbase + gg * 128);
            ulonglong2 vp23 = *(const ulonglong2*)(vbase + gg * 128 + 4);
            ulonglong2 wp   = *(const ulonglong2*)(wbase + gg * 64);
            unsigned long long c2 = c2base[gg];
            unsigned long long tt;
            tt = addp(vp01.x, wp.x) & MASK;  a00 = fmap(c2, tt, a00);
            tt = addp(vp01.x, wp.y) & MASK;  a01 = fmap(c2, tt, a01);
            tt = addp(vp01.y, wp.x) & MASK;  a10 = fmap(c2, tt, a10);
            tt = addp(vp01.y, wp.y) & MASK;  a11 = fmap(c2, tt, a11);
            tt = addp(vp23.x, wp.x) & MASK;  a20 = fmap(c2, tt, a20);
            tt = addp(vp23.x, wp.y) & MASK;  a21 = fmap(c2, tt, a21);
            tt = addp(vp23.y, wp.x) & MASK;  a30 = fmap(c2, tt, a30);
            tt = addp(vp23.y, wp.y) & MASK;  a31 = fmap(c2, tt, a31);
        }

        float4 q4 = *(const float4*)(sQ + tx * 4);
        unsigned long long acc[4][2] = {{a00,a01},{a10,a11},{a20,a21},{a30,a31}};
        #pragma unroll
        for (int r = 0; r < 4; r++) {
            float pr = sP[ty * 4 + r] + pcb;
            float4 res;
            res.x = __uint_as_float((unsigned)(acc[r][0] & 0xffffffffULL)) + pr + q4.x;
            res.y = __uint_as_float((unsigned)(acc[r][0] >> 32))           + pr + q4.y;
            res.z = __uint_as_float((unsigned)(acc[r][1] & 0xffffffffULL)) + pr + q4.z;
            res.w = __uint_as_float((unsigned)(acc[r][1] >> 32))           + pr + q4.w;
            int og = oc * 64 + ty * 4 + r;
            *(float4*)(out + OFF_A + b * 65536 + og * 256 + ic * 64 + tx * 4) = res;
        }
    }
}

// ============================================================
extern "C" void kernel_launch(void* const* d_in, const int* in_sizes, int n_in,
                              void* d_out, int out_size)
{
    const float* ope   = (const float*)d_in[0];
    const float* ins   = (const float*)d_in[1];
    const float* h_in  = (const float*)d_in[2];
    const float* c_in  = (const float*)d_in[3];
    const float* W_ih  = (const float*)d_in[4];
    const float* W_hh  = (const float*)d_in[5];
    const float* b_ih  = (const float*)d_in[6];
    const float* b_hh  = (const float*)d_in[7];
    const float* Wv0   = (const float*)d_in[8];
    const float* bv0   = (const float*)d_in[9];
    const float* Wv1   = (const float*)d_in[10];
    const float* bv1   = (const float*)d_in[11];
    const float* Wv2   = (const float*)d_in[12];
    const float* bv2   = (const float*)d_in[13];
    const float* Wa0   = (const float*)d_in[14];
    const float* ba0   = (const float*)d_in[15];
    const float* Wa1   = (const float*)d_in[16];
    const float* ba1   = (const float*)d_in[17];
    const float* Wa2   = (const float*)d_in[18];
    const float* ba2   = (const float*)d_in[19];
    float* out = (float*)d_out;

    cudaFuncSetAttribute(k_all, cudaFuncAttributeMaxDynamicSharedMemorySize, 99840);

    k_all<<<NBLK, 256, 99840>>>(ope, ins, h_in, c_in, W_ih, W_hh, b_ih, b_hh,
                                Wv0, bv0, Wv1, bv1, Wv2, bv2,
                                Wa0, ba0, Wa1, ba1, Wa2, ba2, out);
}

// round 9
// speedup vs baseline: 1.2709x; 1.2709x over previous
#include <cuda_runtime.h>
#include <math.h>

// B=8, D=64, O=256, I=256, G=128
// Output: V(8) | A(8*65536) | hn(8*64) | cn(8*64)
#define OFF_V  0
#define OFF_A  8
#define OFF_HN 524296
#define OFF_CN 524808

// ---- scratch ----
__device__ float g_hn[8 * 64];
__device__ float g_u[8 * 128];
__device__ float g_pc[8];
__device__ float g_M[4 * 128 * 64];     // m0=Wa1@Wo, m1=Wa1@Wi, m2=Wa1@Ws, m3=Wv1@Wv0
__device__ float g_bba[128];
__device__ float g_bbv[128];
__device__ float g_c1[128];
__device__ float g_c2d[256];
__device__ float g_vvT[8 * 128 * 256];  // [b][g][o]
__device__ float g_wT[8 * 128 * 256];   // [b][g][i]
__device__ float g_PQ[4096];

__device__ __forceinline__ float sigm(float x) { return 1.0f / (1.0f + expf(-x)); }

__device__ __forceinline__ float warp_sum(float v) {
    #pragma unroll
    for (int o = 16; o; o >>= 1) v += __shfl_xor_sync(0xffffffffu, v, o);
    return v;
}

__device__ __forceinline__ unsigned long long addp(unsigned long long a, unsigned long long b) {
    unsigned long long r;
    asm("add.rn.f32x2 %0, %1, %2;" : "=l"(r) : "l"(a), "l"(b));
    return r;
}
__device__ __forceinline__ unsigned long long fmap(unsigned long long a, unsigned long long b, unsigned long long c) {
    unsigned long long r;
    asm("fma.rn.f32x2 %0, %1, %2, %3;" : "=l"(r) : "l"(a), "l"(b), "l"(c));
    return r;
}

// ============================================================
// K1: blocks 0..31 : 4 GEMMs (Wa1@Wo, Wa1@Wi, Wa1@Ws, Wv1@Wv0)
//     block  32    : fused biases + c1/c2d
//     blocks 33..40: per-batch mean / gates / LSTM -> g_hn, out
// dynamic smem 45120 B (GEMM blocks only; attribute opt-in since
// static+dynamic > 48KB)
// ============================================================
__global__ void __launch_bounds__(256) k_setup(
                        const float* __restrict__ ope,
                        const float* __restrict__ h_in,
                        const float* __restrict__ c_in,
                        const float* __restrict__ W_ih,
                        const float* __restrict__ W_hh,
                        const float* __restrict__ b_ih,
                        const float* __restrict__ b_hh,
                        const float* __restrict__ Wv0, const float* __restrict__ bv0,
                        const float* __restrict__ Wv1, const float* __restrict__ bv1,
                        const float* __restrict__ Wa0, const float* __restrict__ ba0,
                        const float* __restrict__ Wa1, const float* __restrict__ ba1,
                        const float* __restrict__ Wa2,
                        float* __restrict__ out)
{
    extern __shared__ float dsm[];
    const int t = threadIdx.x;

    if (blockIdx.x < 32) {
        float* sA = dsm;                 // 16*129
        float* sB = dsm + 16 * 129;      // 128*72
        const int m  = blockIdx.x >> 3;  // 0..3
        const int gc = blockIdx.x & 7;

        const float* Aglob = (m == 3) ? Wv1 : Wa1;
        #pragma unroll
        for (int i = 0; i < 8; i++) {
            int idx = t + i * 256;
            sA[(idx >> 7) * 129 + (idx & 127)] = Aglob[gc * 2048 + idx];
        }
        {
            int hh0 = t >> 4, c4 = t & 15;
            #pragma unroll
            for (int i = 0; i < 8; i++) {
                int hh = hh0 + i * 16;
                const float* src = (m == 3) ? (Wv0 + hh * 64)
                                            : (Wa0 + hh * 192 + ((m == 0) ? 64 : (m == 1) ? 128 : 0));
                float4 v = *(const float4*)(src + c4 * 4);
                *(float4*)(sB + hh * 72 + c4 * 4) = v;
            }
        }
        __syncthreads();

        const int g = t >> 4, dg = t & 15;
        float4 acc = make_float4(0.f, 0.f, 0.f, 0.f);
        const float* arow = sA + g * 129;
        const float* bcol = sB + dg * 4;
        #pragma unroll 8
        for (int hh = 0; hh < 128; hh++) {
            float a = arow[hh];
            float4 bv = *(const float4*)(bcol + hh * 72);
            acc.x += a * bv.x; acc.y += a * bv.y; acc.z += a * bv.z; acc.w += a * bv.w;
        }
        *(float4*)(g_M + m * 8192 + (gc * 16 + g) * 64 + dg * 4) = acc;
        return;
    }

    if (blockIdx.x == 32) {
        __shared__ float sb[256];
        if (t < 128) sb[t] = ba0[t];
        else         sb[t] = bv0[t - 128];
        __syncthreads();
        if (t < 128) {
            float acc = ba1[t];
            const float4* row = (const float4*)(Wa1 + t * 128);
            #pragma unroll 8
            for (int j = 0; j < 32; j++) {
                float4 w4 = row[j];
                float4 x4 = *(const float4*)(sb + j * 4);
                acc += w4.x * x4.x + w4.y * x4.y + w4.z * x4.z + w4.w * x4.w;
            }
            g_bba[t] = acc;
            float w2 = Wa2[t];
            g_c1[t] = 0.505f * w2;
            g_c2d[2 * t]     = 0.495f * w2;
            g_c2d[2 * t + 1] = 0.495f * w2;
        } else {
            int r = t - 128;
            float acc = bv1[r];
            const float4* row = (const float4*)(Wv1 + r * 128);
            #pragma unroll 8
            for (int j = 0; j < 32; j++) {
                float4 w4 = row[j];
                float4 x4 = *(const float4*)(sb + 128 + j * 4);
                acc += w4.x * x4.x + w4.y * x4.y + w4.z * x4.z + w4.w * x4.w;
            }
            g_bbv[r] = acc;
        }
        return;
    }

    // ---- per-batch: mean -> gates (register weights) -> LSTM ----
    __shared__ float sPart[1024];
    __shared__ float s_x[128];
    __shared__ float s_gates[256];
    const int b = blockIdx.x - 33;

    float4 wi[16];
    {
        const float4* pwi = (const float4*)(W_ih + t * 64);
        #pragma unroll
        for (int j = 0; j < 16; j++) wi[j] = pwi[j];
    }

    {
        int dq = t & 15, rc = t >> 4;
        const float* base = ope + (b * 258 + 1 + rc * 16) * 64 + dq * 4;
        float4 s = make_float4(0.f, 0.f, 0.f, 0.f);
        #pragma unroll
        for (int rr = 0; rr < 16; rr++) {
            float4 x = *(const float4*)(base + rr * 64);
            s.x += x.x; s.y += x.y; s.z += x.z; s.w += x.w;
        }
        *(float4*)(sPart + rc * 64 + dq * 4) = s;
    }
    if (t >= 64 && t < 128) s_x[t] = h_in[b * 64 + (t - 64)];
    __syncthreads();
    if (t < 64) {
        float s = 0.f;
        #pragma unroll
        for (int rc = 0; rc < 16; rc++) s += sPart[rc * 64 + t];
        s_x[t] = s * (1.0f / 256.0f);
    }
    __syncthreads();

    float acc = b_ih[t] + b_hh[t];
    #pragma unroll
    for (int j = 0; j < 16; j++) {
        float4 x4 = *(const float4*)(s_x + j * 4);
        acc += wi[j].x * x4.x + wi[j].y * x4.y + wi[j].z * x4.z + wi[j].w * x4.w;
    }
    {
        float4 wh[16];
        const float4* pwh = (const float4*)(W_hh + t * 64);
        #pragma unroll
        for (int j = 0; j < 16; j++) wh[j] = pwh[j];
        #pragma unroll
        for (int j = 0; j < 16; j++) {
            float4 x4 = *(const float4*)(s_x + 64 + j * 4);
            acc += wh[j].x * x4.x + wh[j].y * x4.y + wh[j].z * x4.z + wh[j].w * x4.w;
        }
    }
    s_gates[t] = acc;
    __syncthreads();

    if (t < 64) {
        float ig = sigm(s_gates[t]);
        float fg = sigm(s_gates[64 + t]);
        float gg = tanhf(s_gates[128 + t]);
        float og = sigm(s_gates[192 + t]);
        float cn = fg * c_in[b * 64 + t] + ig * gg;
        float hn = og * tanhf(cn);
        g_hn[b * 64 + t] = hn;
        out[OFF_HN + b * 64 + t] = hn;
        out[OFF_CN + b * 64 + t] = cn;
    }
}

// ============================================================
// K2: blocks 0..255: vv/w rows (transposed, NO u) + fused P'/Q.
//     blocks 256..263: u / pc / V per batch.
// ============================================================
__global__ void __launch_bounds__(128) k_vw(const float* __restrict__ ope,
                                            const float* __restrict__ ins,
                                            const float* __restrict__ Wv2,
                                            const float* __restrict__ bv2,
                                            float* __restrict__ out)
{
    const int t = threadIdx.x;

    if (blockIdx.x >= 256) {
        __shared__ float shn[64];
        __shared__ float spc[128];
        __shared__ float sz[128];
        const int b = blockIdx.x - 256;
        if (t < 64) shn[t] = g_hn[b * 64 + t];
        __syncthreads();

        {
            float acc = g_bba[t];
            const float4* row = (const float4*)(g_M + 2 * 8192 + t * 64);
            #pragma unroll
            for (int j = 0; j < 16; j++) {
                float4 w4 = row[j];
                float4 x4 = *(const float4*)(shn + j * 4);
                acc += w4.x * x4.x + w4.y * x4.y + w4.z * x4.z + w4.w * x4.w;
            }
            g_u[b * 128 + t] = acc;
            spc[t] = g_c1[t] * acc;
        }
        {
            float acc = g_bbv[t];
            const float4* row = (const float4*)(g_M + 3 * 8192 + t * 64);
            #pragma unroll
            for (int j = 0; j < 16; j++) {
                float4 w4 = row[j];
                float4 x4 = *(const float4*)(shn + j * 4);
                acc += w4.x * x4.x + w4.y * x4.y + w4.z * x4.z + w4.w * x4.w;
            }
            sz[t] = (acc >= 0.f) ? acc : 0.01f * acc;
        }
        __syncthreads();
        int w = t >> 5, lane = t & 31;
        if (w == 0) {
            float4 x = *(const float4*)(spc + lane * 4);
            float s = x.x + x.y + x.z + x.w;
            s = warp_sum(s);
            if (lane == 0) g_pc[b] = s;
        } else if (w == 1) {
            float4 x = *(const float4*)(sz + lane * 4);
            float4 ww = *(const float4*)(Wv2 + lane * 4);
            float s = ww.x * x.x + ww.y * x.y + ww.z * x.z + ww.w * x.w;
            s = warp_sum(s);
            if (lane == 0) out[OFF_V + b] = s + bv2[0];
        }
        return;
    }

    __shared__ float sIn[1024];
    __shared__ float sRed[2048];
    const int rbase = blockIdx.x * 16;
    const int g = t;
    const bool isV = (rbase < 2048);
    const int rb = isV ? rbase : (rbase - 2048);
    const int b = rb >> 8;
    const int x0 = rb & 255;

    const float4* Mrow = (const float4*)(g_M + (isV ? 0 : 8192) + g * 64);
    float4 m[16];
    #pragma unroll
    for (int j = 0; j < 16; j++) m[j] = Mrow[j];

    const float4* s4 = (const float4*)(isV ? (ope + (b * 258 + 1 + x0) * 64)
                                           : (ins + (b * 256 + x0) * 64));
    ((float4*)sIn)[g] = s4[g];
    ((float4*)sIn)[g + 128] = s4[g + 128];

    const float c1 = g_c1[g];
    __syncthreads();

    float accs[16];
    #pragma unroll
    for (int r = 0; r < 16; r++) {
        float a = 0.f;
        const float4* ip = (const float4*)(sIn + r * 64);
        #pragma unroll
        for (int j = 0; j < 16; j++) {
            float4 x = ip[j];
            a += m[j].x * x.x + m[j].y * x.y + m[j].z * x.z + m[j].w * x.w;
        }
        accs[r] = a;
        sRed[r * 128 + g] = c1 * a;
    }

    float* dst = (isV ? g_vvT : g_wT) + b * 32768 + g * 256 + x0;
    #pragma unroll
    for (int r4 = 0; r4 < 4; r4++)
        *(float4*)(dst + r4 * 4) = make_float4(accs[r4*4], accs[r4*4+1], accs[r4*4+2], accs[r4*4+3]);

    __syncthreads();
    int ww = g >> 5, lane = g & 31;
    #pragma unroll
    for (int rr = 0; rr < 4; rr++) {
        int row = ww * 4 + rr;
        float4 xx = ((const float4*)(sRed + row * 128))[lane];
        float s = xx.x + xx.y + xx.z + xx.w;
        #pragma unroll
        for (int off = 16; off; off >>= 1) s += __shfl_xor_sync(0xffffffffu, s, off);
        if (lane == 0) g_PQ[rbase + row] = s;
    }
}

// ============================================================
// K3: A tile kernel, packed f32x2; u added at staging, pc in epilogue.
// ============================================================
__global__ void __launch_bounds__(256) k_a(const float* __restrict__ ba2p,
                                           float* __restrict__ out)
{
    extern __shared__ float sm[];
    float* sVd = sm;            // 128*128
    float* sW  = sm + 16384;    // 128*64
    float* sC2 = sm + 24576;    // 256
    float* sP  = sm + 24832;    // 64
    float* sQ  = sm + 24896;    // 64
    const int b = blockIdx.z, oc = blockIdx.y, ic = blockIdx.x;
    const int tid = threadIdx.x;

    const float pcb = g_pc[b] + ba2p[0];

    const float* vsrc = g_vvT + b * 32768 + oc * 64;
    const float* wsrc = g_wT  + b * 32768 + ic * 64;
    const float* usrc = g_u + b * 128;
    #pragma unroll
    for (int l = tid; l < 2048; l += 256) {
        int gg = l >> 4, q = (l & 15) << 2;
        float4 wv = *(const float4*)(wsrc + gg * 256 + q);
        *(float4*)(sW + gg * 64 + q) = wv;
        float uu = usrc[gg];
        float4 vv = *(const float4*)(vsrc + gg * 256 + q);
        vv.x += uu; vv.y += uu; vv.z += uu; vv.w += uu;
        float* vd = sVd + gg * 128 + q * 2;
        ((float4*)vd)[0] = make_float4(vv.x, vv.x, vv.y, vv.y);
        ((float4*)vd)[1] = make_float4(vv.z, vv.z, vv.w, vv.w);
    }
    sC2[tid] = g_c2d[tid & 255];
    if (tid < 64)       sP[tid] = g_PQ[b * 256 + oc * 64 + tid];
    else if (tid < 128) sQ[tid - 64] = g_PQ[2048 + b * 256 + ic * 64 + (tid - 64)];
    __syncthreads();

    const int tx = tid & 15, ty = tid >> 4;
    unsigned long long a00 = 0, a01 = 0, a10 = 0, a11 = 0,
                       a20 = 0, a21 = 0, a30 = 0, a31 = 0;
    const float* vbase = sVd + ty * 8;
    const float* wbase = sW + tx * 4;
    const unsigned long long* c2base = (const unsigned long long*)sC2;
    const unsigned long long MASK = 0x7FFFFFFF7FFFFFFFULL;

    #pragma unroll 4
    for (int gg = 0; gg < 128; gg++) {
        ulonglong2 vp01 = *(const ulonglong2*)(vbase + gg * 128);
        ulonglong2 vp23 = *(const ulonglong2*)(vbase + gg * 128 + 4);
        ulonglong2 wp   = *(const ulonglong2*)(wbase + gg * 64);
        unsigned long long c2 = c2base[gg];
        unsigned long long t;
        t = addp(vp01.x, wp.x) & MASK;  a00 = fmap(c2, t, a00);
        t = addp(vp01.x, wp.y) & MASK;  a01 = fmap(c2, t, a01);
        t = addp(vp01.y, wp.x) & MASK;  a10 = fmap(c2, t, a10);
        t = addp(vp01.y, wp.y) & MASK;  a11 = fmap(c2, t, a11);
        t = addp(vp23.x, wp.x) & MASK;  a20 = fmap(c2, t, a20);
        t = addp(vp23.x, wp.y) & MASK;  a21 = fmap(c2, t, a21);
        t = addp(vp23.y, wp.x) & MASK;  a30 = fmap(c2, t, a30);
        t = addp(vp23.y, wp.y) & MASK;  a31 = fmap(c2, t, a31);
    }

    float4 q4 = *(const float4*)(sQ + tx * 4);
    unsigned long long acc[4][2] = {{a00,a01},{a10,a11},{a20,a21},{a30,a31}};
    #pragma unroll
    for (int r = 0; r < 4; r++) {
        float pr = sP[ty * 4 + r] + pcb;
        float4 res;
        res.x = __uint_as_float((unsigned)(acc[r][0] & 0xffffffffULL)) + pr + q4.x;
        res.y = __uint_as_float((unsigned)(acc[r][0] >> 32))           + pr + q4.y;
        res.z = __uint_as_float((unsigned)(acc[r][1] & 0xffffffffULL)) + pr + q4.z;
        res.w = __uint_as_float((unsigned)(acc[r][1] >> 32))           + pr + q4.w;
        int og = oc * 64 + ty * 4 + r;
        *(float4*)(out + OFF_A + b * 65536 + og * 256 + ic * 64 + tx * 4) = res;
    }
}

// ============================================================
extern "C" void kernel_launch(void* const* d_in, const int* in_sizes, int n_in,
                              void* d_out, int out_size)
{
    const float* ope   = (const float*)d_in[0];
    const float* ins   = (const float*)d_in[1];
    const float* h_in  = (const float*)d_in[2];
    const float* c_in  = (const float*)d_in[3];
    const float* W_ih  = (const float*)d_in[4];
    const float* W_hh  = (const float*)d_in[5];
    const float* b_ih  = (const float*)d_in[6];
    const float* b_hh  = (const float*)d_in[7];
    const float* Wv0   = (const float*)d_in[8];
    const float* bv0   = (const float*)d_in[9];
    const float* Wv1   = (const float*)d_in[10];
    const float* bv1   = (const float*)d_in[11];
    const float* Wv2   = (const float*)d_in[12];
    const float* bv2   = (const float*)d_in[13];
    const float* Wa0   = (const float*)d_in[14];
    const float* ba0   = (const float*)d_in[15];
    const float* Wa1   = (const float*)d_in[16];
    const float* ba1   = (const float*)d_in[17];
    const float* Wa2   = (const float*)d_in[18];
    const float* ba2   = (const float*)d_in[19];
    float* out = (float*)d_out;

    // 45120 B dynamic + ~5.6KB static > 48KB combined -> must opt in.
    cudaFuncSetAttribute(k_setup, cudaFuncAttributeMaxDynamicSharedMemorySize, 46080);
    cudaFuncSetAttribute(k_a, cudaFuncAttributeMaxDynamicSharedMemorySize, 99840);

    k_setup<<<41, 256, 45120>>>(ope, h_in, c_in, W_ih, W_hh, b_ih, b_hh,
                                Wv0, bv0, Wv1, bv1, Wa0, ba0, Wa1, ba1, Wa2, out);
    k_vw<<<264, 128>>>(ope, ins, Wv2, bv2, out);
    k_a<<<dim3(4, 4, 8), 256, 99840>>>(ba2, out);
}